// round 2
// baseline (speedup 1.0000x reference)
#include <cuda_runtime.h>

#define N_NODES 50000
#define N_EDGES 800000
#define DIMC    128      // H*D
#define TM      64       // GEMM row tile

// ---------------- device scratch (no allocations allowed) ----------------
__device__ float g_Q[(size_t)N_NODES * DIMC];
__device__ float g_K[(size_t)N_NODES * DIMC];
__device__ float g_V[(size_t)N_NODES * DIMC];
__device__ int   g_cnt [N_NODES];
__device__ int   g_off [N_NODES + 1];
__device__ int   g_cur [N_NODES];
__device__ int   g_perm[N_EDGES];
__device__ int   g_is64;

// ---------------- index dtype detection + accessor ----------------
// If src buffer is int64, every odd 32-bit word is a hi-word of a value
// < 50000 -> zero. If int32, odd words are indices (almost surely nonzero).
__global__ void detect_kernel(const void* src) {
    const int* w = (const int*)src;
    int acc = 0;
#pragma unroll
    for (int i = 0; i < 64; i++) acc |= w[2 * i + 1];
    if (threadIdx.x == 0) g_is64 = (acc == 0) ? 1 : 0;
}

__device__ __forceinline__ int edge_idx(const void* p, int i) {
    if (g_is64) return (int)((const long long*)p)[i];
    return ((const int*)p)[i];
}

// ---------------- counting sort by dst ----------------
__global__ void zero_cnt_kernel() {
    int i = blockIdx.x * blockDim.x + threadIdx.x;
    if (i < N_NODES) g_cnt[i] = 0;
}

__global__ void hist_kernel(const void* __restrict__ dst) {
    int i = blockIdx.x * blockDim.x + threadIdx.x;
    if (i < N_EDGES) atomicAdd(&g_cnt[edge_idx(dst, i)], 1);
}

__global__ void scan_kernel() {
    __shared__ int sdata[1024];
    __shared__ int carry;
    int tid = threadIdx.x;
    if (tid == 0) carry = 0;
    __syncthreads();
    for (int base = 0; base < N_NODES; base += 1024) {
        int i = base + tid;
        int v = (i < N_NODES) ? g_cnt[i] : 0;
        sdata[tid] = v;
        __syncthreads();
        for (int off = 1; off < 1024; off <<= 1) {
            int t   = sdata[tid];
            int add = (tid >= off) ? sdata[tid - off] : 0;
            __syncthreads();
            sdata[tid] = t + add;
            __syncthreads();
        }
        int excl = carry + sdata[tid] - v;
        if (i < N_NODES) { g_off[i] = excl; g_cur[i] = excl; }
        __syncthreads();
        if (tid == 0) carry += sdata[1023];
        __syncthreads();
    }
    if (tid == 0) g_off[N_NODES] = carry;
}

__global__ void scatter_kernel(const void* __restrict__ dst) {
    int i = blockIdx.x * blockDim.x + threadIdx.x;
    if (i < N_EDGES) {
        int d = edge_idx(dst, i);
        int p = atomicAdd(&g_cur[d], 1);
        g_perm[p] = i;
    }
}

// ---------------- fp32 GEMM: C[M,128] = A[M,128] @ W[128,128] + bias ----------------
// Block = 256 threads, 64-row tile, full K=128, full N=128.
// Shared: aT [128][64] (k-major, 32KB) + ws [128][128] (64KB) = 96KB dynamic.
// Transpose store mapping (r = idx&63) keeps STS conflict-free (lanes span banks).
// Thread (16x16 grid): rows tr..tr+3, cols {tc..tc+3, tc+64..tc+67} -> LDS.128.
__global__ __launch_bounds__(256, 2) void gemm_bias_kernel(
    const float* __restrict__ A, const float* __restrict__ W,
    const float* __restrict__ bias, float* __restrict__ C, int M)
{
    extern __shared__ float sh[];
    float* aT = sh;               // [128][TM]
    float* ws = sh + 128 * TM;    // [128][128]
    int tid  = threadIdx.x;
    int row0 = blockIdx.x * TM;

    const float4* W4 = (const float4*)W;
    float4* ws4 = (float4*)ws;
#pragma unroll
    for (int i = 0; i < 16; i++) ws4[tid + i * 256] = W4[tid + i * 256];

#pragma unroll
    for (int i = 0; i < 8; i++) {
        int idx = tid + i * 256;          // 0..2047
        int r   = idx & 63;               // row in tile
        int k4  = idx >> 6;               // float4 chunk 0..31
        float4 val = make_float4(0.f, 0.f, 0.f, 0.f);
        int row = row0 + r;
        if (row < M) val = ((const float4*)A)[(size_t)row * 32 + k4];
        aT[(k4 * 4 + 0) * TM + r] = val.x;
        aT[(k4 * 4 + 1) * TM + r] = val.y;
        aT[(k4 * 4 + 2) * TM + r] = val.z;
        aT[(k4 * 4 + 3) * TM + r] = val.w;
    }
    __syncthreads();

    int tr = (tid >> 4) * 4;
    int tc = (tid & 15) * 4;
    float acc[4][8];
#pragma unroll
    for (int r = 0; r < 4; r++)
#pragma unroll
        for (int c = 0; c < 8; c++) acc[r][c] = 0.f;

    const float* ap = &aT[tr];
    const float* wp = &ws[tc];
#pragma unroll 8
    for (int k = 0; k < 128; k++) {
        float4 a  = *(const float4*)ap;  ap += TM;
        float4 b0 = *(const float4*)wp;
        float4 b1 = *(const float4*)(wp + 64);  wp += 128;
        float av[4] = {a.x, a.y, a.z, a.w};
        float bv[8] = {b0.x, b0.y, b0.z, b0.w, b1.x, b1.y, b1.z, b1.w};
#pragma unroll
        for (int r = 0; r < 4; r++)
#pragma unroll
            for (int c = 0; c < 8; c++) acc[r][c] += av[r] * bv[c];
    }

    float4 bb0 = *(const float4*)&bias[tc];
    float4 bb1 = *(const float4*)&bias[tc + 64];
#pragma unroll
    for (int r = 0; r < 4; r++) {
        int row = row0 + tr + r;
        if (row < M) {
            float4 o0 = make_float4(acc[r][0] + bb0.x, acc[r][1] + bb0.y,
                                    acc[r][2] + bb0.z, acc[r][3] + bb0.w);
            float4 o1 = make_float4(acc[r][4] + bb1.x, acc[r][5] + bb1.y,
                                    acc[r][6] + bb1.z, acc[r][7] + bb1.w);
            *(float4*)&C[(size_t)row * 128 + tc]      = o0;
            *(float4*)&C[(size_t)row * 128 + tc + 64] = o1;
        }
    }
}

// ---------------- edge kernel: e_out = e@We + be + (K[src].Q[dst])/4 ----------------
__global__ __launch_bounds__(256, 2) void edge_kernel(
    const float* __restrict__ Emat, const float* __restrict__ We,
    const float* __restrict__ be,
    const void* __restrict__ src, const void* __restrict__ dst,
    float* __restrict__ eout)
{
    extern __shared__ float sh[];
    float* aT = sh;
    float* ws = sh + 128 * TM;
    __shared__ int   s_src[TM];
    __shared__ int   s_dst[TM];
    __shared__ float s_dot[TM * 8];
    int tid  = threadIdx.x;
    int row0 = blockIdx.x * TM;

    const float4* W4 = (const float4*)We;
    float4* ws4 = (float4*)ws;
#pragma unroll
    for (int i = 0; i < 16; i++) ws4[tid + i * 256] = W4[tid + i * 256];

#pragma unroll
    for (int i = 0; i < 8; i++) {
        int idx = tid + i * 256;
        int r   = idx & 63;
        int k4  = idx >> 6;
        int row = row0 + r;
        float4 val = ((const float4*)Emat)[(size_t)row * 32 + k4];  // 800000 % 64 == 0
        aT[(k4 * 4 + 0) * TM + r] = val.x;
        aT[(k4 * 4 + 1) * TM + r] = val.y;
        aT[(k4 * 4 + 2) * TM + r] = val.z;
        aT[(k4 * 4 + 3) * TM + r] = val.w;
    }
    if (tid < TM) {
        int row = row0 + tid;
        s_src[tid] = edge_idx(src, row);
        s_dst[tid] = edge_idx(dst, row);
    }
    __syncthreads();

    // per-(row, head) dot of K[src] and Q[dst]  (512 tasks / 256 threads)
#pragma unroll
    for (int t = tid; t < TM * 8; t += 256) {
        int r  = t >> 3;
        int hh = t & 7;
        const float4* kp = (const float4*)&g_K[(size_t)s_src[r] * 128 + hh * 16];
        const float4* qp = (const float4*)&g_Q[(size_t)s_dst[r] * 128 + hh * 16];
        float d = 0.f;
#pragma unroll
        for (int i = 0; i < 4; i++) {
            float4 kv = kp[i], qv = qp[i];
            d += kv.x * qv.x + kv.y * qv.y + kv.z * qv.z + kv.w * qv.w;
        }
        s_dot[t] = d * 0.25f;   // 1/sqrt(D), D=16
    }
    __syncthreads();

    int tr = (tid >> 4) * 4;
    int tc = (tid & 15) * 4;
    float acc[4][8];
#pragma unroll
    for (int r = 0; r < 4; r++)
#pragma unroll
        for (int c = 0; c < 8; c++) acc[r][c] = 0.f;

    const float* ap = &aT[tr];
    const float* wp = &ws[tc];
#pragma unroll 8
    for (int k = 0; k < 128; k++) {
        float4 a  = *(const float4*)ap;  ap += TM;
        float4 b0 = *(const float4*)wp;
        float4 b1 = *(const float4*)(wp + 64);  wp += 128;
        float av[4] = {a.x, a.y, a.z, a.w};
        float bv[8] = {b0.x, b0.y, b0.z, b0.w, b1.x, b1.y, b1.z, b1.w};
#pragma unroll
        for (int r = 0; r < 4; r++)
#pragma unroll
            for (int c = 0; c < 8; c++) acc[r][c] += av[r] * bv[c];
    }

    float4 bb0 = *(const float4*)&be[tc];
    float4 bb1 = *(const float4*)&be[tc + 64];
    int h0 = tc >> 4;
    int h1 = (tc + 64) >> 4;
#pragma unroll
    for (int r = 0; r < 4; r++) {
        int row = row0 + tr + r;
        float d0 = s_dot[(tr + r) * 8 + h0];
        float d1 = s_dot[(tr + r) * 8 + h1];
        float4 o0 = make_float4(acc[r][0] + bb0.x + d0, acc[r][1] + bb0.y + d0,
                                acc[r][2] + bb0.z + d0, acc[r][3] + bb0.w + d0);
        float4 o1 = make_float4(acc[r][4] + bb1.x + d1, acc[r][5] + bb1.y + d1,
                                acc[r][6] + bb1.z + d1, acc[r][7] + bb1.w + d1);
        *(float4*)&eout[(size_t)row * 128 + tc]      = o0;
        *(float4*)&eout[(size_t)row * 128 + tc + 64] = o1;
    }
}

// ---------------- node kernel: online softmax over incoming edges ----------------
// One block per dst node, one thread per (h,d) component. Single pass over e_out.
__global__ void node_kernel(const void* __restrict__ src,
                            const float* __restrict__ eout,
                            float* __restrict__ wV)
{
    int n = blockIdx.x;
    int c = threadIdx.x;
    int beg = g_off[n], end = g_off[n + 1];
    if (beg == end) { wV[(size_t)n * 128 + c] = 0.f; return; }

    float m = -3.402823466e38f;   // -FLT_MAX
    float s = 0.f, num = 0.f;

    int e = g_perm[beg];
    float sc = eout[(size_t)e * 128 + c];
    float v  = g_V[(size_t)edge_idx(src, e) * 128 + c];

    for (int j = beg; j < end; j++) {
        float sc2 = 0.f, v2 = 0.f;
        if (j + 1 < end) {                       // prefetch next edge
            int e2 = g_perm[j + 1];
            sc2 = eout[(size_t)e2 * 128 + c];
            v2  = g_V[(size_t)edge_idx(src, e2) * 128 + c];
        }
        float mn = fmaxf(m, sc);
        float r  = __expf(m - mn);
        float w  = __expf(sc - mn);
        s   = s * r + w;
        num = num * r + v * w;
        m   = mn;
        sc = sc2; v = v2;
    }
    wV[(size_t)n * 128 + c] = num / s;
}

// ---------------- launch ----------------
extern "C" void kernel_launch(void* const* d_in, const int* in_sizes, int n_in,
                              void* d_out, int out_size)
{
    const float* h  = (const float*)d_in[0];
    const float* e  = (const float*)d_in[1];
    const float* Wq = (const float*)d_in[2];
    const float* bq = (const float*)d_in[3];
    const float* Wk = (const float*)d_in[4];
    const float* bk = (const float*)d_in[5];
    const float* Wv = (const float*)d_in[6];
    const float* bv = (const float*)d_in[7];
    const float* We = (const float*)d_in[8];
    const float* be = (const float*)d_in[9];
    const void*  src = d_in[10];
    const void*  dst = d_in[11];

    float* wV   = (float*)d_out;                         // [N, H, D]
    float* eout = wV + (size_t)N_NODES * DIMC;           // [E, H, D]

    size_t shmem = (size_t)(128 * TM + 128 * 128) * sizeof(float);   // 96 KB
    cudaFuncSetAttribute(gemm_bias_kernel, cudaFuncAttributeMaxDynamicSharedMemorySize, (int)shmem);
    cudaFuncSetAttribute(edge_kernel,      cudaFuncAttributeMaxDynamicSharedMemorySize, (int)shmem);

    void *pQ, *pK, *pV;
    cudaGetSymbolAddress(&pQ, g_Q);
    cudaGetSymbolAddress(&pK, g_K);
    cudaGetSymbolAddress(&pV, g_V);

    // index dtype detection (int32 vs int64), then counting sort by dst
    detect_kernel<<<1, 32>>>(src);
    zero_cnt_kernel<<<(N_NODES + 255) / 256, 256>>>();
    hist_kernel<<<(N_EDGES + 255) / 256, 256>>>(dst);
    scan_kernel<<<1, 1024>>>();
    scatter_kernel<<<(N_EDGES + 255) / 256, 256>>>(dst);

    // projections
    int gblocks = (N_NODES + TM - 1) / TM;
    gemm_bias_kernel<<<gblocks, 256, shmem>>>(h, Wq, bq, (float*)pQ, N_NODES);
    gemm_bias_kernel<<<gblocks, 256, shmem>>>(h, Wk, bk, (float*)pK, N_NODES);
    gemm_bias_kernel<<<gblocks, 256, shmem>>>(h, Wv, bv, (float*)pV, N_NODES);

    // fused edge projection + attention score -> e_out
    edge_kernel<<<N_EDGES / TM, 256, shmem>>>(e, We, be, src, dst, eout);

    // per-node online softmax + weighted V sum -> wV
    node_kernel<<<N_NODES, DIMC>>>(src, eout, wV);
}

// round 3
// speedup vs baseline: 1.4930x; 1.4930x over previous
#include <cuda_runtime.h>
#include <cuda_bf16.h>

#define N_NODES 50000
#define N_EDGES 800000
#define DIMC    128
#define KV      384          // virtual K = 3 * 128 (hi*hi + hi*lo + lo*hi)
#define A_STRIDE 136         // padded bf16 stride (conflict-free frags)
#define B_STRIDE 408         // padded bf16 stride (conflict-free frags)
#define NTILES_QKV 391       // ceil(50000/128)
#define NTILES_E   6250      // 800000/128
#define NBLK_SCAN  49        // ceil(50000/1024)
#define GRID_PERSIST 148

// ---------------- device scratch ----------------
__device__ float g_Q[(size_t)N_NODES * DIMC];
__device__ float g_K[(size_t)N_NODES * DIMC];
__device__ float g_V[(size_t)N_NODES * DIMC];
__device__ __nv_bfloat16 g_Wt[4 * 128 * KV];    // split weights: [m][n][384]
__device__ int   g_cnt [N_NODES];
__device__ int   g_off [N_NODES + 1];
__device__ int   g_cur [N_NODES];
__device__ int   g_perm[N_EDGES];
__device__ int   g_bsum[NBLK_SCAN];
__device__ int   g_is64;

// ---------------- index dtype detection + accessor ----------------
__global__ void detect_kernel(const void* src) {
    const int* w = (const int*)src;
    int acc = 0;
#pragma unroll
    for (int i = 0; i < 64; i++) acc |= w[2 * i + 1];
    if (threadIdx.x == 0) g_is64 = (acc == 0) ? 1 : 0;
}

__device__ __forceinline__ int edge_idx(const void* p, int i) {
    if (g_is64) return (int)((const long long*)p)[i];
    return ((const int*)p)[i];
}

// ---------------- counting sort by dst ----------------
__global__ void zero_cnt_kernel() {
    int i = blockIdx.x * blockDim.x + threadIdx.x;
    if (i < N_NODES) g_cnt[i] = 0;
}

__global__ void hist_kernel(const void* __restrict__ dst) {
    int i = blockIdx.x * blockDim.x + threadIdx.x;
    if (i < N_EDGES) atomicAdd(&g_cnt[edge_idx(dst, i)], 1);
}

__global__ void scan1_kernel() {            // block-local exclusive scan
    __shared__ int sdata[1024];
    int b = blockIdx.x, tid = threadIdx.x;
    int i = b * 1024 + tid;
    int v = (i < N_NODES) ? g_cnt[i] : 0;
    sdata[tid] = v;
    __syncthreads();
    for (int off = 1; off < 1024; off <<= 1) {
        int t   = sdata[tid];
        int add = (tid >= off) ? sdata[tid - off] : 0;
        __syncthreads();
        sdata[tid] = t + add;
        __syncthreads();
    }
    if (i < N_NODES) g_off[i] = sdata[tid] - v;
    if (tid == 1023) g_bsum[b] = sdata[1023];
}

__global__ void scan2_kernel() {            // scan of 49 block totals
    if (threadIdx.x == 0) {
        int run = 0;
        for (int b = 0; b < NBLK_SCAN; b++) { int t = g_bsum[b]; g_bsum[b] = run; run += t; }
        g_off[N_NODES] = run;
    }
}

__global__ void scan3_kernel() {            // add block bases
    int b = blockIdx.x;
    int i = b * 1024 + threadIdx.x;
    if (i < N_NODES) {
        int o = g_off[i] + g_bsum[b];
        g_off[i] = o;
        g_cur[i] = o;
    }
}

__global__ void scatter_kernel(const void* __restrict__ dst) {
    int i = blockIdx.x * blockDim.x + threadIdx.x;
    if (i < N_EDGES) {
        int d = edge_idx(dst, i);
        int p = atomicAdd(&g_cur[d], 1);
        g_perm[p] = i;
    }
}

// ---------------- weight split prep: g_Wt[m][n][k''] ----------------
// B'' layout over virtual K: [0:128)=hi(W), [128:256)=lo(W), [256:384)=hi(W)
__global__ void prep_kernel(const float* __restrict__ Wq, const float* __restrict__ Wk,
                            const float* __restrict__ Wv, const float* __restrict__ We)
{
    int idx = blockIdx.x * 256 + threadIdx.x;
    if (idx >= 4 * 128 * KV) return;
    int m   = idx / (128 * KV);
    int rem = idx - m * (128 * KV);
    int n   = rem / KV;
    int kk  = rem - n * KV;
    int seg = kk >> 7;
    int k   = kk & 127;
    const float* W = (m == 0) ? Wq : (m == 1) ? Wk : (m == 2) ? Wv : We;
    float w = W[k * 128 + n];
    __nv_bfloat16 hi = __float2bfloat16(w);
    __nv_bfloat16 val = (seg == 1) ? __float2bfloat16(w - __bfloat162float(hi)) : hi;
    g_Wt[idx] = val;
}

// ---------------- bf16 tensor-core mma helper ----------------
__device__ __forceinline__ void mma_bf16(float* c, const unsigned* a, unsigned b0, unsigned b1) {
    asm volatile(
        "mma.sync.aligned.m16n8k16.row.col.f32.bf16.bf16.f32 "
        "{%0,%1,%2,%3}, {%4,%5,%6,%7}, {%8,%9}, {%0,%1,%2,%3};"
        : "+f"(c[0]), "+f"(c[1]), "+f"(c[2]), "+f"(c[3])
        : "r"(a[0]), "r"(a[1]), "r"(a[2]), "r"(a[3]), "r"(b0), "r"(b1));
}

// A tile fill: fp32 gmem -> hi/lo bf16 smem (padded, coalesced LDG.128)
__device__ __forceinline__ void fill_A(const float* __restrict__ A, int row0, int M,
                                       __nv_bfloat16* Ahi, __nv_bfloat16* Alo, int tid)
{
#pragma unroll
    for (int i = 0; i < 16; i++) {
        int idx = tid + i * 256;            // 0..4095 (128 rows x 32 float4)
        int r   = idx >> 5;
        int k4  = idx & 31;
        float4 v = make_float4(0.f, 0.f, 0.f, 0.f);
        if (row0 + r < M) v = ((const float4*)A)[(size_t)(row0 + r) * 32 + k4];
        __nv_bfloat16 hx = __float2bfloat16(v.x), hy = __float2bfloat16(v.y);
        __nv_bfloat16 hz = __float2bfloat16(v.z), hw = __float2bfloat16(v.w);
        __nv_bfloat16 lx = __float2bfloat16(v.x - __bfloat162float(hx));
        __nv_bfloat16 ly = __float2bfloat16(v.y - __bfloat162float(hy));
        __nv_bfloat16 lz = __float2bfloat16(v.z - __bfloat162float(hz));
        __nv_bfloat16 lw = __float2bfloat16(v.w - __bfloat162float(hw));
        __nv_bfloat162* ph = (__nv_bfloat162*)&Ahi[r * A_STRIDE + k4 * 4];
        __nv_bfloat162* pl = (__nv_bfloat162*)&Alo[r * A_STRIDE + k4 * 4];
        __nv_bfloat162 t;
        t.x = hx; t.y = hy; ph[0] = t;
        t.x = hz; t.y = hw; ph[1] = t;
        t.x = lx; t.y = ly; pl[0] = t;
        t.x = lz; t.y = lw; pl[1] = t;
    }
}

// ---------------- persistent tensor-core GEMM: C = A@W + bias ----------------
__global__ __launch_bounds__(256, 1) void gemm_tc_kernel(
    const float* __restrict__ A, const __nv_bfloat16* __restrict__ Bt,
    const float* __restrict__ bias, float* __restrict__ C, int M, int ntiles)
{
    extern __shared__ __nv_bfloat16 sm[];
    __nv_bfloat16* Ahi = sm;
    __nv_bfloat16* Alo = sm + 128 * A_STRIDE;
    __nv_bfloat16* Bs  = sm + 2 * 128 * A_STRIDE;
    int tid = threadIdx.x;

    // stage B'' once (persists across tiles)
    for (int i = tid; i < 128 * KV / 2; i += 256) {
        int n  = i / (KV / 2);
        int kw = i - n * (KV / 2);
        ((unsigned*)&Bs[n * B_STRIDE])[kw] = ((const unsigned*)&Bt[n * KV])[kw];
    }
    __syncthreads();

    int warp = tid >> 5, lane = tid & 31;
    int ty = lane >> 2, tx = lane & 3;
    int wm = warp & 3, wn = warp >> 2;

    for (int tile = blockIdx.x; tile < ntiles; tile += gridDim.x) {
        int row0 = tile * 128;
        fill_A(A, row0, M, Ahi, Alo, tid);
        __syncthreads();

        float acc[2][8][4];
#pragma unroll
        for (int mt = 0; mt < 2; mt++)
#pragma unroll
            for (int nt = 0; nt < 8; nt++)
#pragma unroll
                for (int q = 0; q < 4; q++) acc[mt][nt][q] = 0.f;

        for (int kc = 0; kc < 24; kc++) {
            const __nv_bfloat16* Ab = (kc < 16) ? Ahi : Alo;
            int ak = (kc & 7) * 16;
            unsigned a[2][4];
#pragma unroll
            for (int mt = 0; mt < 2; mt++) {
                const __nv_bfloat16* ap = &Ab[(wm * 32 + mt * 16 + ty) * A_STRIDE + ak + 2 * tx];
                a[mt][0] = *(const unsigned*)ap;
                a[mt][1] = *(const unsigned*)(ap + 8 * A_STRIDE);
                a[mt][2] = *(const unsigned*)(ap + 8);
                a[mt][3] = *(const unsigned*)(ap + 8 * A_STRIDE + 8);
            }
            int bk = kc * 16 + 2 * tx;
#pragma unroll
            for (int nt = 0; nt < 8; nt++) {
                const __nv_bfloat16* bp = &Bs[(wn * 64 + nt * 8 + ty) * B_STRIDE + bk];
                unsigned b0 = *(const unsigned*)bp;
                unsigned b1 = *(const unsigned*)(bp + 8);
                mma_bf16(acc[0][nt], a[0], b0, b1);
                mma_bf16(acc[1][nt], a[1], b0, b1);
            }
        }

#pragma unroll
        for (int nt = 0; nt < 8; nt++) {
            int col = wn * 64 + nt * 8 + 2 * tx;
            float2 bb = *(const float2*)&bias[col];
#pragma unroll
            for (int mt = 0; mt < 2; mt++) {
                int r = row0 + wm * 32 + mt * 16 + ty;
                if (r < M) {
                    float2 o; o.x = acc[mt][nt][0] + bb.x; o.y = acc[mt][nt][1] + bb.y;
                    *(float2*)&C[(size_t)r * 128 + col] = o;
                }
                if (r + 8 < M) {
                    float2 o; o.x = acc[mt][nt][2] + bb.x; o.y = acc[mt][nt][3] + bb.y;
                    *(float2*)&C[(size_t)(r + 8) * 128 + col] = o;
                }
            }
        }
        __syncthreads();
    }
}

// ---------------- persistent edge kernel: eout = e@We + be + dot ----------------
__global__ __launch_bounds__(256, 1) void edge_tc_kernel(
    const float* __restrict__ Emat, const __nv_bfloat16* __restrict__ Bt,
    const float* __restrict__ be,
    const void* __restrict__ src, const void* __restrict__ dst,
    float* __restrict__ eout)
{
    extern __shared__ __nv_bfloat16 sm[];
    __nv_bfloat16* Ahi = sm;
    __nv_bfloat16* Alo = sm + 128 * A_STRIDE;
    __nv_bfloat16* Bs  = sm + 2 * 128 * A_STRIDE;
    __shared__ int   s_src[128];
    __shared__ int   s_dst[128];
    __shared__ float s_dot[128 * 8];
    int tid = threadIdx.x;

    for (int i = tid; i < 128 * KV / 2; i += 256) {
        int n  = i / (KV / 2);
        int kw = i - n * (KV / 2);
        ((unsigned*)&Bs[n * B_STRIDE])[kw] = ((const unsigned*)&Bt[n * KV])[kw];
    }
    __syncthreads();

    int warp = tid >> 5, lane = tid & 31;
    int ty = lane >> 2, tx = lane & 3;
    int wm = warp & 3, wn = warp >> 2;

    for (int tile = blockIdx.x; tile < NTILES_E; tile += gridDim.x) {
        int row0 = tile * 128;
        fill_A(Emat, row0, N_EDGES, Ahi, Alo, tid);
        if (tid < 128) {
            s_src[tid] = edge_idx(src, row0 + tid);
            s_dst[tid] = edge_idx(dst, row0 + tid);
        }
        __syncthreads();

        // per-(row, head) dot of K[src], Q[dst]: 1024 tasks
#pragma unroll
        for (int t = tid; t < 128 * 8; t += 256) {
            int r  = t >> 3;
            int hh = t & 7;
            const float4* kp = (const float4*)&g_K[(size_t)s_src[r] * 128 + hh * 16];
            const float4* qp = (const float4*)&g_Q[(size_t)s_dst[r] * 128 + hh * 16];
            float d = 0.f;
#pragma unroll
            for (int i = 0; i < 4; i++) {
                float4 kv = kp[i], qv = qp[i];
                d += kv.x * qv.x + kv.y * qv.y + kv.z * qv.z + kv.w * qv.w;
            }
            s_dot[t] = d * 0.25f;    // 1/sqrt(D), D=16
        }
        __syncthreads();

        float acc[2][8][4];
#pragma unroll
        for (int mt = 0; mt < 2; mt++)
#pragma unroll
            for (int nt = 0; nt < 8; nt++)
#pragma unroll
                for (int q = 0; q < 4; q++) acc[mt][nt][q] = 0.f;

        for (int kc = 0; kc < 24; kc++) {
            const __nv_bfloat16* Ab = (kc < 16) ? Ahi : Alo;
            int ak = (kc & 7) * 16;
            unsigned a[2][4];
#pragma unroll
            for (int mt = 0; mt < 2; mt++) {
                const __nv_bfloat16* ap = &Ab[(wm * 32 + mt * 16 + ty) * A_STRIDE + ak + 2 * tx];
                a[mt][0] = *(const unsigned*)ap;
                a[mt][1] = *(const unsigned*)(ap + 8 * A_STRIDE);
                a[mt][2] = *(const unsigned*)(ap + 8);
                a[mt][3] = *(const unsigned*)(ap + 8 * A_STRIDE + 8);
            }
            int bk = kc * 16 + 2 * tx;
#pragma unroll
            for (int nt = 0; nt < 8; nt++) {
                const __nv_bfloat16* bp = &Bs[(wn * 64 + nt * 8 + ty) * B_STRIDE + bk];
                unsigned b0 = *(const unsigned*)bp;
                unsigned b1 = *(const unsigned*)(bp + 8);
                mma_bf16(acc[0][nt], a[0], b0, b1);
                mma_bf16(acc[1][nt], a[1], b0, b1);
            }
        }

#pragma unroll
        for (int nt = 0; nt < 8; nt++) {
            int col  = wn * 64 + nt * 8 + 2 * tx;
            int head = col >> 4;
            float2 bb = *(const float2*)&be[col];
#pragma unroll
            for (int mt = 0; mt < 2; mt++) {
                int rl = wm * 32 + mt * 16 + ty;
                int r  = row0 + rl;
                float d0 = s_dot[rl * 8 + head];
                float d1 = s_dot[(rl + 8) * 8 + head];
                float2 o;
                o.x = acc[mt][nt][0] + bb.x + d0; o.y = acc[mt][nt][1] + bb.y + d0;
                *(float2*)&eout[(size_t)r * 128 + col] = o;
                o.x = acc[mt][nt][2] + bb.x + d1; o.y = acc[mt][nt][3] + bb.y + d1;
                *(float2*)&eout[(size_t)(r + 8) * 128 + col] = o;
            }
        }
        __syncthreads();
    }
}

// ---------------- node kernel: online softmax over incoming edges ----------------
__global__ void node_kernel(const void* __restrict__ src,
                            const float* __restrict__ eout,
                            float* __restrict__ wV)
{
    int n = blockIdx.x;
    int c = threadIdx.x;
    int beg = g_off[n], end = g_off[n + 1];
    if (beg == end) { wV[(size_t)n * 128 + c] = 0.f; return; }

    float m = -3.402823466e38f;
    float s = 0.f, num = 0.f;

    int e = g_perm[beg];
    float sc = eout[(size_t)e * 128 + c];
    float v  = g_V[(size_t)edge_idx(src, e) * 128 + c];

    for (int j = beg; j < end; j++) {
        float sc2 = 0.f, v2 = 0.f;
        if (j + 1 < end) {
            int e2 = g_perm[j + 1];
            sc2 = eout[(size_t)e2 * 128 + c];
            v2  = g_V[(size_t)edge_idx(src, e2) * 128 + c];
        }
        float mn = fmaxf(m, sc);
        float r  = __expf(m - mn);
        float w  = __expf(sc - mn);
        s   = s * r + w;
        num = num * r + v * w;
        m   = mn;
        sc = sc2; v = v2;
    }
    wV[(size_t)n * 128 + c] = num / s;
}

// ---------------- launch ----------------
extern "C" void kernel_launch(void* const* d_in, const int* in_sizes, int n_in,
                              void* d_out, int out_size)
{
    const float* h  = (const float*)d_in[0];
    const float* e  = (const float*)d_in[1];
    const float* Wq = (const float*)d_in[2];
    const float* bq = (const float*)d_in[3];
    const float* Wk = (const float*)d_in[4];
    const float* bk = (const float*)d_in[5];
    const float* Wv = (const float*)d_in[6];
    const float* bv = (const float*)d_in[7];
    const float* We = (const float*)d_in[8];
    const float* be = (const float*)d_in[9];
    const void*  src = d_in[10];
    const void*  dst = d_in[11];

    float* wV   = (float*)d_out;
    float* eout = wV + (size_t)N_NODES * DIMC;

    size_t shmem = (size_t)(2 * 128 * A_STRIDE + 128 * B_STRIDE) * sizeof(__nv_bfloat16); // 174080
    cudaFuncSetAttribute(gemm_tc_kernel, cudaFuncAttributeMaxDynamicSharedMemorySize, (int)shmem);
    cudaFuncSetAttribute(edge_tc_kernel, cudaFuncAttributeMaxDynamicSharedMemorySize, (int)shmem);

    void *pQ, *pK, *pV, *pWt;
    cudaGetSymbolAddress(&pQ, g_Q);
    cudaGetSymbolAddress(&pK, g_K);
    cudaGetSymbolAddress(&pV, g_V);
    cudaGetSymbolAddress(&pWt, g_Wt);
    const __nv_bfloat16* Wt = (const __nv_bfloat16*)pWt;

    // index dtype detection, counting sort by dst (parallel scan)
    detect_kernel<<<1, 32>>>(src);
    zero_cnt_kernel<<<(N_NODES + 255) / 256, 256>>>();
    hist_kernel<<<(N_EDGES + 255) / 256, 256>>>(dst);
    scan1_kernel<<<NBLK_SCAN, 1024>>>();
    scan2_kernel<<<1, 32>>>();
    scan3_kernel<<<NBLK_SCAN, 1024>>>();
    scatter_kernel<<<(N_EDGES + 255) / 256, 256>>>(dst);

    // split weights to bf16 hi/lo (B'' virtual-K layout)
    prep_kernel<<<(4 * 128 * KV + 255) / 256, 256>>>(Wq, Wk, Wv, We);

    // projections (tensor cores, persistent)
    gemm_tc_kernel<<<GRID_PERSIST, 256, shmem>>>(h, Wt + 0 * 128 * KV, bq, (float*)pQ, N_NODES, NTILES_QKV);
    gemm_tc_kernel<<<GRID_PERSIST, 256, shmem>>>(h, Wt + 1 * 128 * KV, bk, (float*)pK, N_NODES, NTILES_QKV);
    gemm_tc_kernel<<<GRID_PERSIST, 256, shmem>>>(h, Wt + 2 * 128 * KV, bv, (float*)pV, N_NODES, NTILES_QKV);

    // fused edge projection + attention score
    edge_tc_kernel<<<GRID_PERSIST, 256, shmem>>>(e, Wt + 3 * 128 * KV, be, src, dst, eout);

    // per-node online softmax + weighted V sum
    node_kernel<<<N_NODES, DIMC>>>(src, eout, wV);
}